// round 1
// baseline (speedup 1.0000x reference)
#include <cuda_runtime.h>

#define BB 256
#define RR 2592
#define LL 32
#define CC 16
#define BL 8192           // BB*LL
#define RL 82944          // RR*LL
#define UHAT_ELEMS (RR*BB*LL)

// Scratch (device globals: no allocation in kernel_launch)
__device__ float g_uhat[UHAT_ELEMS];   // layout [r][b][l], 85 MB
__device__ float g_s[BL];
__device__ float g_v[BL];
__device__ float g_c[RR];
__device__ float g_blog[RR];
__device__ float g_a[RR];

// ---------------------------------------------------------------------------
// Re-init state every call (graph replays must be deterministic)
__global__ void k_init() {
    int i = blockIdx.x * blockDim.x + threadIdx.x;   // 0..8191
    if (i < RR) { g_blog[i] = 0.0f; g_c[i] = 1.0f / (float)RR; }
    if (i < BL) g_s[i] = 0.0f;
}

// ---------------------------------------------------------------------------
// u_hat[b,r,l] = sum_c W[r,l,c] * x[b,r,c]; one block per r.
__global__ __launch_bounds__(256) void k_uhat(const float* __restrict__ x,
                                              const float* __restrict__ W) {
    __shared__ float4 xs4[BB * 4];      // x[:, r, :] as float4 rows, 16 KB
    __shared__ float  Ws[32 * 17];      // padded to avoid bank conflicts
    const int r = blockIdx.x;
    const int t = threadIdx.x;

    // Load W row r: 512 floats
    for (int i = t; i < 512; i += 256) {
        int l = i >> 4, c = i & 15;
        Ws[l * 17 + c] = W[r * 512 + i];
    }
    // Load x slice: 256 rows x 4 float4
    const float4* x4 = (const float4*)x;
    #pragma unroll
    for (int k = 0; k < 4; k++) {
        int idx = k * 256 + t;           // 0..1023 ; idx = b*4 + c4
        int b = idx >> 2, c4 = idx & 3;
        xs4[idx] = x4[(b * RR + r) * 4 + c4];
    }
    __syncthreads();

    const int lane = t & 31, warp = t >> 5;
    float w[16];
    #pragma unroll
    for (int c = 0; c < 16; c++) w[c] = Ws[lane * 17 + c];

    #pragma unroll 4
    for (int it = 0; it < 32; it++) {
        int b = it * 8 + warp;
        float4 xa = xs4[b * 4 + 0];
        float4 xb = xs4[b * 4 + 1];
        float4 xc = xs4[b * 4 + 2];
        float4 xd = xs4[b * 4 + 3];
        float acc = w[0] * xa.x;
        acc = fmaf(w[1],  xa.y, acc);  acc = fmaf(w[2],  xa.z, acc);
        acc = fmaf(w[3],  xa.w, acc);  acc = fmaf(w[4],  xb.x, acc);
        acc = fmaf(w[5],  xb.y, acc);  acc = fmaf(w[6],  xb.z, acc);
        acc = fmaf(w[7],  xb.w, acc);  acc = fmaf(w[8],  xc.x, acc);
        acc = fmaf(w[9],  xc.y, acc);  acc = fmaf(w[10], xc.z, acc);
        acc = fmaf(w[11], xc.w, acc);  acc = fmaf(w[12], xd.x, acc);
        acc = fmaf(w[13], xd.y, acc);  acc = fmaf(w[14], xd.z, acc);
        acc = fmaf(w[15], xd.w, acc);
        g_uhat[r * BL + b * LL + lane] = acc;
    }
}

// ---------------------------------------------------------------------------
// s[b,l] += sum_{r in chunk} c[r] * u_hat[r,b,l]
#define RCH 144
__global__ __launch_bounds__(256) void k_s() {
    __shared__ float cs[RCH];
    const int t = threadIdx.x;
    const int r0 = blockIdx.y * RCH;
    if (t < RCH) cs[t] = g_c[r0 + t];
    __syncthreads();

    const int warp = t >> 5, lane = t & 31;
    const int b = blockIdx.x * 8 + warp;
    const float* base = g_uhat + (size_t)r0 * BL + b * LL + lane;

    float a0 = 0.0f, a1 = 0.0f;
    #pragma unroll 8
    for (int i = 0; i < RCH; i += 2) {
        a0 += cs[i]     * base[(size_t)i * BL];
        a1 += cs[i + 1] * base[(size_t)(i + 1) * BL];
    }
    atomicAdd(&g_s[b * LL + lane], a0 + a1);
}

// ---------------------------------------------------------------------------
// v = squash(s) elementwise; re-zero s for the next iteration
__global__ void k_squash() {
    int i = blockIdx.x * 256 + threadIdx.x;
    float s = g_s[i];
    float sq = s * s;
    g_v[i] = sq * s / ((1.0f + sq) * sqrtf(sq));
    g_s[i] = 0.0f;
}

// ---------------------------------------------------------------------------
// a[r] = (1/B) * sum_{b,l} u_hat[r,b,l] * v[b,l];  4 r's per block
__global__ __launch_bounds__(256) void k_a() {
    __shared__ float vsm[BL];     // 32 KB
    __shared__ float red[8];
    const int t = threadIdx.x;
    for (int i = t; i < BL; i += 256) vsm[i] = g_v[i];
    __syncthreads();

    const int warp = t >> 5, lane = t & 31;
    for (int rr = 0; rr < 4; rr++) {
        const int r = blockIdx.x * 4 + rr;
        const float* u = g_uhat + (size_t)r * BL;
        float acc = 0.0f;
        #pragma unroll 8
        for (int i = t; i < BL; i += 256) acc += u[i] * vsm[i];
        #pragma unroll
        for (int o = 16; o; o >>= 1) acc += __shfl_xor_sync(0xffffffffu, acc, o);
        if (lane == 0) red[warp] = acc;
        __syncthreads();
        if (t == 0) {
            float tot = 0.0f;
            #pragma unroll
            for (int w8 = 0; w8 < 8; w8++) tot += red[w8];
            g_a[r] = tot * (1.0f / (float)BB);
        }
        __syncthreads();
    }
}

// ---------------------------------------------------------------------------
// b += a ; c = softmax(b). Single block, 1024 threads, 3 elems/thread.
__global__ __launch_bounds__(1024) void k_update() {
    __shared__ float red[32];
    const int t = threadIdx.x;
    float vals[3];
    float mx = -1e30f;
    #pragma unroll
    for (int k = 0; k < 3; k++) {
        int i = t + k * 1024;
        if (i < RR) {
            float bn = g_blog[i] + g_a[i];
            g_blog[i] = bn;
            vals[k] = bn;
            mx = fmaxf(mx, bn);
        } else vals[k] = -1e30f;
    }
    // block max
    #pragma unroll
    for (int o = 16; o; o >>= 1) mx = fmaxf(mx, __shfl_xor_sync(0xffffffffu, mx, o));
    if ((t & 31) == 0) red[t >> 5] = mx;
    __syncthreads();
    if (t < 32) {
        float m = red[t];
        #pragma unroll
        for (int o = 16; o; o >>= 1) m = fmaxf(m, __shfl_xor_sync(0xffffffffu, m, o));
        if (t == 0) red[0] = m;
    }
    __syncthreads();
    const float bmax = red[0];
    __syncthreads();

    float ex[3];
    float es = 0.0f;
    #pragma unroll
    for (int k = 0; k < 3; k++) {
        int i = t + k * 1024;
        ex[k] = (i < RR) ? expf(vals[k] - bmax) : 0.0f;
        es += ex[k];
    }
    #pragma unroll
    for (int o = 16; o; o >>= 1) es += __shfl_xor_sync(0xffffffffu, es, o);
    if ((t & 31) == 0) red[t >> 5] = es;
    __syncthreads();
    if (t < 32) {
        float s = red[t];
        #pragma unroll
        for (int o = 16; o; o >>= 1) s += __shfl_xor_sync(0xffffffffu, s, o);
        if (t == 0) red[0] = s;
    }
    __syncthreads();
    const float inv = 1.0f / red[0];
    #pragma unroll
    for (int k = 0; k < 3; k++) {
        int i = t + k * 1024;
        if (i < RR) g_c[i] = ex[k] * inv;
    }
}

// ---------------------------------------------------------------------------
// Write outputs: out[0:8192] = v ; out[8192 + b*R*L + r*L + l] = c[r]*u_hat[r,b,l]
__global__ __launch_bounds__(256) void k_out(float* __restrict__ out) {
    const int t = threadIdx.x;
    if (blockIdx.x == 0) {
        for (int i = t; i < BL; i += 256) out[i] = g_v[i];
    }
    const int warp = t >> 5, lane = t & 31;
    const int gw = blockIdx.x * 8 + warp;       // 20736 warps, 32 rows each
    float* uo = out + BL;
    #pragma unroll 4
    for (int i = 0; i < 32; i++) {
        int q = gw * 32 + i;                    // (r,b) row index: q = r*256 + b
        int r = q >> 8, b = q & 255;
        float val = __ldg(&g_c[r]) * g_uhat[(size_t)q * 32 + lane];
        uo[(size_t)b * RL + r * 32 + lane] = val;
    }
}

// ---------------------------------------------------------------------------
extern "C" void kernel_launch(void* const* d_in, const int* in_sizes, int n_in,
                              void* d_out, int out_size) {
    const float* x = (const float*)d_in[0];   // (B, R, C)
    const float* W = (const float*)d_in[1];   // (1, R, 1, L, C)
    float* out = (float*)d_out;

    k_init<<<32, 256>>>();
    k_uhat<<<RR, 256>>>(x, W);
    for (int it = 0; it < 3; it++) {
        k_s<<<dim3(32, 18), 256>>>();
        k_squash<<<32, 256>>>();
        if (it < 2) {
            k_a<<<648, 256>>>();
            k_update<<<1, 1024>>>();
        }
    }
    k_out<<<RR, 256>>>(out);
}

// round 2
// speedup vs baseline: 1.2796x; 1.2796x over previous
#include <cuda_runtime.h>
#include <cuda_fp16.h>

#define BB 256
#define RR 2592
#define LL 32
#define CC 16
#define BL 8192           // BB*LL
#define RL 82944          // RR*LL
#define UHAT_ELEMS (RR*BB*LL)

// Scratch (device globals: no allocation in kernel_launch)
__device__ __half g_uhat[UHAT_ELEMS];  // layout [r][b][l], fp16, 42.5 MB
__device__ float g_s[BL];
__device__ float g_c[RR];
__device__ float g_blog[RR];
__device__ float g_a[RR];

__device__ __forceinline__ float squashf(float s) {
    float sq = s * s;
    return sq * s / ((1.0f + sq) * sqrtf(sq));
}

// ---------------------------------------------------------------------------
// Re-init state every call (graph replays must be deterministic)
__global__ void k_init() {
    int i = blockIdx.x * blockDim.x + threadIdx.x;   // 0..8191
    if (i < RR) { g_blog[i] = 0.0f; g_c[i] = 1.0f / (float)RR; }
    if (i < BL) g_s[i] = 0.0f;
}

// ---------------------------------------------------------------------------
// u_hat[r,b,l] = sum_c W[r,l,c] * x[b,r,c]; one block per r. fp16 store.
__global__ __launch_bounds__(256) void k_uhat(const float* __restrict__ x,
                                              const float* __restrict__ W) {
    __shared__ float4 xs4[BB * 4];      // x[:, r, :] as float4 rows, 16 KB
    __shared__ float  Ws[32 * 17];      // padded to avoid bank conflicts
    const int r = blockIdx.x;
    const int t = threadIdx.x;

    for (int i = t; i < 512; i += 256) {
        int l = i >> 4, c = i & 15;
        Ws[l * 17 + c] = W[r * 512 + i];
    }
    const float4* x4 = (const float4*)x;
    #pragma unroll
    for (int k = 0; k < 4; k++) {
        int idx = k * 256 + t;           // idx = b*4 + c4
        int b = idx >> 2, c4 = idx & 3;
        xs4[idx] = x4[(b * RR + r) * 4 + c4];
    }
    __syncthreads();

    const int lane = t & 31, warp = t >> 5;
    float w[16];
    #pragma unroll
    for (int c = 0; c < 16; c++) w[c] = Ws[lane * 17 + c];

    #pragma unroll 4
    for (int it = 0; it < 32; it++) {
        int b = it * 8 + warp;
        float4 xa = xs4[b * 4 + 0];
        float4 xb = xs4[b * 4 + 1];
        float4 xc = xs4[b * 4 + 2];
        float4 xd = xs4[b * 4 + 3];
        float acc = w[0] * xa.x;
        acc = fmaf(w[1],  xa.y, acc);  acc = fmaf(w[2],  xa.z, acc);
        acc = fmaf(w[3],  xa.w, acc);  acc = fmaf(w[4],  xb.x, acc);
        acc = fmaf(w[5],  xb.y, acc);  acc = fmaf(w[6],  xb.z, acc);
        acc = fmaf(w[7],  xb.w, acc);  acc = fmaf(w[8],  xc.x, acc);
        acc = fmaf(w[9],  xc.y, acc);  acc = fmaf(w[10], xc.z, acc);
        acc = fmaf(w[11], xc.w, acc);  acc = fmaf(w[12], xd.x, acc);
        acc = fmaf(w[13], xd.y, acc);  acc = fmaf(w[14], xd.z, acc);
        acc = fmaf(w[15], xd.w, acc);
        g_uhat[(size_t)r * BL + b * LL + lane] = __float2half_rn(acc);
    }
}

// ---------------------------------------------------------------------------
// s[b,l] += sum_{r in chunk} c[r] * u_hat[r,b,l]
// half2 lanes: lanes 0-15 -> row b, lanes 16-31 -> row b+1 (128B/warp loads)
#define RCH 144
__global__ __launch_bounds__(256) void k_s() {
    __shared__ float cs[RCH];
    const int t = threadIdx.x;
    const int r0 = blockIdx.y * RCH;
    if (t < RCH) cs[t] = g_c[r0 + t];
    __syncthreads();

    const int warp = t >> 5, lane = t & 31;
    const int pairidx = lane & 15;            // half2 index within the row
    const int b = blockIdx.x * 16 + warp * 2 + (lane >> 4);
    const __half2* base = (const __half2*)g_uhat
                        + ((size_t)r0 * BB + b) * 16 + pairidx;

    float2 a0 = make_float2(0.f, 0.f), a1 = make_float2(0.f, 0.f);
    #pragma unroll 8
    for (int i = 0; i < RCH; i += 2) {
        float2 u0 = __half22float2(base[(size_t)i * (BB * 16)]);
        float2 u1 = __half22float2(base[(size_t)(i + 1) * (BB * 16)]);
        a0.x = fmaf(cs[i],     u0.x, a0.x);
        a0.y = fmaf(cs[i],     u0.y, a0.y);
        a1.x = fmaf(cs[i + 1], u1.x, a1.x);
        a1.y = fmaf(cs[i + 1], u1.y, a1.y);
    }
    atomicAdd(&g_s[b * LL + pairidx * 2],     a0.x + a1.x);
    atomicAdd(&g_s[b * LL + pairidx * 2 + 1], a0.y + a1.y);
}

// ---------------------------------------------------------------------------
// a[r] = (1/B) * sum_{b,l} u_hat[r,b,l] * squash(s)[b,l];  4 r's per block
__global__ __launch_bounds__(256) void k_a() {
    __shared__ float2 vsm[BL / 2];   // 32 KB, v as float2 pairs
    __shared__ float red[8];
    const int t = threadIdx.x;
    const float2* s2 = (const float2*)g_s;
    for (int i = t; i < BL / 2; i += 256) {
        float2 s = s2[i];
        vsm[i] = make_float2(squashf(s.x), squashf(s.y));
    }
    __syncthreads();

    const int warp = t >> 5, lane = t & 31;
    for (int rr = 0; rr < 4; rr++) {
        const int r = blockIdx.x * 4 + rr;
        const __half2* u = (const __half2*)g_uhat + (size_t)r * (BL / 2);
        float acc = 0.0f;
        #pragma unroll 8
        for (int i = t; i < BL / 2; i += 256) {
            float2 uf = __half22float2(u[i]);
            float2 vf = vsm[i];
            acc = fmaf(uf.x, vf.x, acc);
            acc = fmaf(uf.y, vf.y, acc);
        }
        #pragma unroll
        for (int o = 16; o; o >>= 1) acc += __shfl_xor_sync(0xffffffffu, acc, o);
        if (lane == 0) red[warp] = acc;
        __syncthreads();
        if (t == 0) {
            float tot = 0.0f;
            #pragma unroll
            for (int w8 = 0; w8 < 8; w8++) tot += red[w8];
            g_a[r] = tot * (1.0f / (float)BB);
        }
        __syncthreads();
    }
}

// ---------------------------------------------------------------------------
// b += a ; c = softmax(b); zero g_s for the next routing iteration.
__global__ __launch_bounds__(1024) void k_update() {
    __shared__ float red[32];
    const int t = threadIdx.x;
    float vals[3];
    float mx = -1e30f;
    #pragma unroll
    for (int k = 0; k < 3; k++) {
        int i = t + k * 1024;
        if (i < RR) {
            float bn = g_blog[i] + g_a[i];
            g_blog[i] = bn;
            vals[k] = bn;
            mx = fmaxf(mx, bn);
        } else vals[k] = -1e30f;
    }
    #pragma unroll
    for (int k = 0; k < 8; k++) g_s[t + k * 1024] = 0.0f;

    #pragma unroll
    for (int o = 16; o; o >>= 1) mx = fmaxf(mx, __shfl_xor_sync(0xffffffffu, mx, o));
    if ((t & 31) == 0) red[t >> 5] = mx;
    __syncthreads();
    if (t < 32) {
        float m = red[t];
        #pragma unroll
        for (int o = 16; o; o >>= 1) m = fmaxf(m, __shfl_xor_sync(0xffffffffu, m, o));
        if (t == 0) red[0] = m;
    }
    __syncthreads();
    const float bmax = red[0];
    __syncthreads();

    float ex[3];
    float es = 0.0f;
    #pragma unroll
    for (int k = 0; k < 3; k++) {
        int i = t + k * 1024;
        ex[k] = (i < RR) ? expf(vals[k] - bmax) : 0.0f;
        es += ex[k];
    }
    #pragma unroll
    for (int o = 16; o; o >>= 1) es += __shfl_xor_sync(0xffffffffu, es, o);
    if ((t & 31) == 0) red[t >> 5] = es;
    __syncthreads();
    if (t < 32) {
        float s = red[t];
        #pragma unroll
        for (int o = 16; o; o >>= 1) s += __shfl_xor_sync(0xffffffffu, s, o);
        if (t == 0) red[0] = s;
    }
    __syncthreads();
    const float inv = 1.0f / red[0];
    #pragma unroll
    for (int k = 0; k < 3; k++) {
        int i = t + k * 1024;
        if (i < RR) g_c[i] = ex[k] * inv;
    }
}

// ---------------------------------------------------------------------------
// out[0:8192] = squash(s) ; out[8192 + b*R*L + r*L + l] = c[r]*u_hat[r,b,l]
// Two rows per warp per iteration (half2 in, float2 out — 128B both ways).
__global__ __launch_bounds__(256) void k_out(float* __restrict__ out) {
    const int t = threadIdx.x;
    if (blockIdx.x == 0) {
        for (int i = t; i < BL; i += 256) out[i] = squashf(g_s[i]);
    }
    const int warp = t >> 5, lane = t & 31;
    const int pairidx = lane & 15, brow = lane >> 4;
    const int gw = blockIdx.x * 8 + warp;       // 10368 warps, 64 rows each
    float* uo = out + BL;
    #pragma unroll 4
    for (int i = 0; i < 32; i++) {
        int q = (gw * 32 + i) * 2 + brow;       // (r,b) row: q = r*256 + b
        int r = q >> 8, b = q & 255;
        float2 uf = __half22float2(
            ((const __half2*)g_uhat)[(size_t)q * 16 + pairidx]);
        float cr = __ldg(&g_c[r]);
        float2 o2 = make_float2(cr * uf.x, cr * uf.y);
        ((float2*)(uo + (size_t)b * RL + r * 32))[pairidx] = o2;
    }
}

// ---------------------------------------------------------------------------
extern "C" void kernel_launch(void* const* d_in, const int* in_sizes, int n_in,
                              void* d_out, int out_size) {
    const float* x = (const float*)d_in[0];   // (B, R, C)
    const float* W = (const float*)d_in[1];   // (1, R, 1, L, C)
    float* out = (float*)d_out;

    k_init<<<32, 256>>>();
    k_uhat<<<RR, 256>>>(x, W);
    for (int it = 0; it < 3; it++) {
        k_s<<<dim3(16, 18), 256>>>();
        if (it < 2) {
            k_a<<<648, 256>>>();
            k_update<<<1, 1024>>>();
        }
    }
    k_out<<<1296, 256>>>(out);
}